// round 2
// baseline (speedup 1.0000x reference)
#include <cuda_runtime.h>

#define HH 256
#define WW 256
#define BB 2
#define CC 21
#define KF 7
#define SPAN 3
#define KK 49
#define HW (HH*WW)

// Tile config: 32 wide x 8 tall, 256 threads, one thread per pixel.
#define TX 32
#define TY 8
#define HALO_W (TX + 2*SPAN)   // 38
#define HALO_H (TY + 2*SPAN)   // 14
#define HALO_N (HALO_W * HALO_H)  // 532

// Scratch (no allocations allowed -> __device__ globals)
__device__ float g_gauss[BB*KK*HW];       // [b][k][h][w]
__device__ float g_lgu[BB*CC*HW];         // log-softmax(unary)
__device__ float g_pred[2][BB*CC*HW];     // ping-pong prediction buffers

// ---------------------------------------------------------------------------
// Kernel A: pairwise Gaussian weights (pos + color), computed once.
// ---------------------------------------------------------------------------
__global__ __launch_bounds__(256) void gauss_kernel(const float* __restrict__ img) {
    __shared__ float simg[3][HALO_H][HALO_W];
    const int b  = blockIdx.z;
    const int tx = threadIdx.x, ty = threadIdx.y;
    const int tid = ty * TX + tx;
    const int h0 = blockIdx.y * TY, w0 = blockIdx.x * TX;

    // load img halo tile (scaled by 1/13)
    for (int idx = tid; idx < 3 * HALO_N; idx += 256) {
        int ch = idx / HALO_N;
        int rem = idx % HALO_N;
        int r = rem / HALO_W, c = rem % HALO_W;
        int gh = h0 - SPAN + r, gw = w0 - SPAN + c;
        float v = 0.f;
        if (gh >= 0 && gh < HH && gw >= 0 && gw < WW)
            v = img[(b*3 + ch)*HW + gh*WW + gw] * (1.f/13.f);
        simg[ch][r][c] = v;
    }
    __syncthreads();

    const int h = h0 + ty, w = w0 + tx;
    const float c0 = simg[0][ty+SPAN][tx+SPAN];
    const float c1 = simg[1][ty+SPAN][tx+SPAN];
    const float c2 = simg[2][ty+SPAN][tx+SPAN];

    #pragma unroll
    for (int i = 0; i < KF; i++) {
        #pragma unroll
        for (int j = 0; j < KF; j++) {
            const int k = i*KF + j;
            const int dh = i - SPAN, dw = j - SPAN;
            const int nh = h + dh, nw = w + dw;
            float g = 0.f;
            if (nh >= 0 && nh < HH && nw >= 0 && nw < WW) {
                float d0 = simg[0][ty+i][tx+j] - c0;
                float d1 = simg[1][ty+i][tx+j] - c1;
                float d2 = simg[2][ty+i][tx+j] - c2;
                float col = __expf(-0.5f*(d0*d0 + d1*d1 + d2*d2));
                float pos = __expf(-(float)(dh*dh + dw*dw) * (0.5f/9.f));
                g = 3.f*pos + 10.f*col;
            }
            g_gauss[(b*KK + k)*HW + h*WW + w] = g;
        }
    }
}

// ---------------------------------------------------------------------------
// Kernel B: log_softmax over classes; seeds prediction buffer 0.
// ---------------------------------------------------------------------------
__global__ __launch_bounds__(256) void lsm_kernel(const float* __restrict__ unary) {
    int idx = blockIdx.x * blockDim.x + threadIdx.x;   // over B*HW
    if (idx >= BB*HW) return;
    int b = idx / HW, p = idx % HW;
    const float* u = unary + b*CC*HW + p;

    float v[CC];
    float mx = -1e30f;
    #pragma unroll
    for (int c = 0; c < CC; c++) { v[c] = u[c*HW]; mx = fmaxf(mx, v[c]); }
    float s = 0.f;
    #pragma unroll
    for (int c = 0; c < CC; c++) s += __expf(v[c] - mx);
    float lse = mx + __logf(s);
    #pragma unroll
    for (int c = 0; c < CC; c++) {
        float lg = v[c] - lse;
        g_lgu[(b*CC + c)*HW + p]      = lg;
        g_pred[0][(b*CC + c)*HW + p]  = lg;
    }
}

// ---------------------------------------------------------------------------
// Kernel C: one mean-field iteration.
// gaussian held in 49 registers (shared across all 21 classes);
// per-class prediction halo tile staged in smem (conflict-free row reads).
// Halo-load geometry (smem offset, gmem offset, in-bounds predicate) is
// class-invariant, so it is computed ONCE per thread before the class loop.
// ---------------------------------------------------------------------------
__global__ __launch_bounds__(256) void iter_kernel(const float* __restrict__ wt,
                                                   float* __restrict__ dout,
                                                   int it) {
    __shared__ float sp[HALO_N];   // 532 floats
    __shared__ float sw[CC];

    const float* __restrict__ pin = g_pred[it & 1];
    float* __restrict__ pout = (it == 4) ? dout : g_pred[(it + 1) & 1];
    const int do_sm = (it != 4);

    const int b  = blockIdx.z;
    const int tx = threadIdx.x, ty = threadIdx.y;
    const int tid = ty * TX + tx;
    const int h0 = blockIdx.y * TY, w0 = blockIdx.x * TX;
    const int h = h0 + ty, w = w0 + tx;
    const int pix = h*WW + w;

    if (tid < CC) sw[tid] = wt[tid];

    // Precompute halo-load plan (<=3 loads per thread; 532 = 2*256 + 20)
    int   ld_smem[3];
    int   ld_gmem[3];
    float ld_ok[3];
    int   n_ld = 0;
    #pragma unroll
    for (int base = 0; base < HALO_N; base += 256) {
        int idx = base + tid;
        if (idx < HALO_N) {
            int r = idx / HALO_W, c = idx % HALO_W;
            int gh = h0 - SPAN + r, gw = w0 - SPAN + c;
            bool ok = (gh >= 0 && gh < HH && gw >= 0 && gw < WW);
            int ghc = min(max(gh, 0), HH-1);
            int gwc = min(max(gw, 0), WW-1);
            ld_smem[n_ld] = idx;
            ld_gmem[n_ld] = ghc*WW + gwc;   // clamped: always safe to load
            ld_ok[n_ld]   = ok ? 1.f : 0.f;
            n_ld++;
        }
    }

    // gaussian weights for this pixel -> registers
    float gr[KK];
    #pragma unroll
    for (int k = 0; k < KK; k++)
        gr[k] = g_gauss[(b*KK + k)*HW + pix];

    float m[CC];
    #pragma unroll
    for (int c = 0; c < CC; c++) {
        __syncthreads();   // protect sp from previous class / publish sw
        const float* __restrict__ pc = pin + (b*CC + c)*HW;
        for (int q = 0; q < n_ld; q++)
            sp[ld_smem[q]] = pc[ld_gmem[q]] * ld_ok[q];
        __syncthreads();

        float acc = 0.f;
        #pragma unroll
        for (int i = 0; i < KF; i++) {
            #pragma unroll
            for (int j = 0; j < KF; j++)
                acc = fmaf(gr[i*KF + j], sp[(ty+i)*HALO_W + tx + j], acc);
        }
        float wc = sw[c];
        float lg = g_lgu[(b*CC + c)*HW + pix];
        m[c] = (1.f - wc)*lg + wc*acc;
    }

    if (do_sm) {
        float mx = m[0];
        #pragma unroll
        for (int c = 1; c < CC; c++) mx = fmaxf(mx, m[c]);
        float s = 0.f;
        #pragma unroll
        for (int c = 0; c < CC; c++) { m[c] = __expf(m[c] - mx); s += m[c]; }
        float inv = 1.f / s;
        #pragma unroll
        for (int c = 0; c < CC; c++) m[c] *= inv;
    }
    #pragma unroll
    for (int c = 0; c < CC; c++)
        pout[(b*CC + c)*HW + pix] = m[c];
}

// ---------------------------------------------------------------------------
extern "C" void kernel_launch(void* const* d_in, const int* in_sizes, int n_in,
                              void* d_out, int out_size) {
    // identify inputs by element count (robust to metadata ordering)
    const float* unary  = nullptr;   // 2*21*256*256 = 2752512
    const float* img    = nullptr;   // 2*3*256*256  = 393216
    const float* weight = nullptr;   // 21
    for (int i = 0; i < n_in; i++) {
        if (in_sizes[i] == BB*CC*HW)      unary  = (const float*)d_in[i];
        else if (in_sizes[i] == BB*3*HW)  img    = (const float*)d_in[i];
        else if (in_sizes[i] == CC)       weight = (const float*)d_in[i];
        // num_iter (1 elem) is fixed at 5 by the problem setup; graph
        // structure cannot depend on device-resident values.
    }
    float* out = (float*)d_out;

    dim3 blk(TX, TY);
    dim3 grd(WW/TX, HH/TY, BB);           // 8 x 32 x 2 = 512 blocks

    gauss_kernel<<<grd, blk>>>(img);
    lsm_kernel<<<(BB*HW + 255)/256, 256>>>(unary);
    for (int it = 0; it < 5; it++)
        iter_kernel<<<grd, blk>>>(weight, out, it);
}